// round 15
// baseline (speedup 1.0000x reference)
#include <cuda_runtime.h>
#include <cuda_bf16.h>
#include <math.h>
#include <stdint.h>

#define T_DIM 32768
#define OBS_DIM 256
#define H_DIM 512
#define NOBJ_DIM 4
#define CH_L 64
#define NCHUNK (T_DIM / CH_L)   // 512

// ---------------- device-global scratch (no runtime allocation) -------------
__device__ float g_ABar[(size_t)T_DIM * H_DIM];
__device__ float g_Bx  [(size_t)T_DIM * H_DIM];
__device__ float g_C   [(size_t)T_DIM * H_DIM];
__device__ float g_y   [(size_t)T_DIM * H_DIM];
__device__ __nv_bfloat16 g_Xhi[(size_t)T_DIM * H_DIM];
__device__ __nv_bfloat16 g_Xlo[(size_t)T_DIM * H_DIM];
__device__ __nv_bfloat16 g_Wstk[(size_t)2048 * 1536];   // [n_packed][Kv]
__device__ float g_negA[H_DIM];
__device__ float g_chA [NCHUNK * H_DIM];
__device__ float g_chH [NCHUNK * H_DIM];
__device__ float g_carry[NCHUNK * H_DIM];

// ---------------- PTX helpers (plain sm_103 features only) ------------------
__device__ __forceinline__ uint32_t smem_u32(const void* p) {
    uint32_t a;
    asm("{ .reg .u64 t; cvta.to.shared.u64 t, %1; cvt.u32.u64 %0, t; }" : "=r"(a) : "l"(p));
    return a;
}
__device__ __forceinline__ void cp16(uint32_t saddr, const void* gaddr) {
    asm volatile("cp.async.cg.shared.global [%0], [%1], 16;" :: "r"(saddr), "l"(gaddr) : "memory");
}
__device__ __forceinline__ void cp_commit() {
    asm volatile("cp.async.commit_group;" ::: "memory");
}
__device__ __forceinline__ void cp_wait2() {
    asm volatile("cp.async.wait_group 2;" ::: "memory");
}
__device__ __forceinline__ void ldm_x4(uint32_t addr, uint32_t& r0, uint32_t& r1,
                                       uint32_t& r2, uint32_t& r3) {
    asm volatile("ldmatrix.sync.aligned.m8n8.x4.shared.b16 {%0,%1,%2,%3}, [%4];"
                 : "=r"(r0), "=r"(r1), "=r"(r2), "=r"(r3) : "r"(addr));
}
__device__ __forceinline__ void mma_bf16(float* d, const uint32_t* a, const uint32_t* b) {
    asm volatile(
        "mma.sync.aligned.m16n8k16.row.col.f32.bf16.bf16.f32 "
        "{%0,%1,%2,%3}, {%4,%5,%6,%7}, {%8,%9}, {%0,%1,%2,%3};"
        : "+f"(d[0]), "+f"(d[1]), "+f"(d[2]), "+f"(d[3])
        : "r"(a[0]), "r"(a[1]), "r"(a[2]), "r"(a[3]), "r"(b[0]), "r"(b[1]));
}

// ---------------- preprocessing kernels -------------------------------------
// Pack 4 weight mats [K,H] fp32 -> Wstk[n][Kv] bf16, n = 4*h+p, Kv = 3K:
// seg0: hi(W), seg1: lo(W), seg2: hi(W)   (pairs with A = [Xhi | Xhi | Xlo])
// Coalesced: 32x32 (k,h) tile via smem transpose. grid (K/32, H/32, 4), block (32,8).
__global__ __launch_bounds__(256) void pack_w_kernel(
    const float* __restrict__ Win, const float* __restrict__ WB,
    const float* __restrict__ WC,  const float* __restrict__ Wd,
    int Kdim, __nv_bfloat16* __restrict__ Wstk)
{
    __shared__ __nv_bfloat16 shi[32][33];
    __shared__ __nv_bfloat16 slo[32][33];
    const int p  = blockIdx.z;
    const int k0 = blockIdx.x * 32;
    const int h0 = blockIdx.y * 32;
    const int tx = threadIdx.x, ty = threadIdx.y;
    const int Kv = 3 * Kdim;
    const float* Wp = (p == 0) ? Win : (p == 1) ? WB : (p == 2) ? WC : Wd;

    #pragma unroll
    for (int i = 0; i < 4; i++) {
        int k = k0 + ty + 8 * i;
        float w = Wp[(size_t)k * H_DIM + h0 + tx];    // coalesced along h
        __nv_bfloat16 hi = __float2bfloat16(w);
        shi[ty + 8 * i][tx] = hi;
        slo[ty + 8 * i][tx] = __float2bfloat16(w - __bfloat162float(hi));
    }
    __syncthreads();

    #pragma unroll
    for (int i = 0; i < 4; i++) {
        int row = ty + 8 * i;                          // h offset in tile
        size_t base = (size_t)(4 * (h0 + row) + p) * Kv;
        __nv_bfloat16 hi = shi[tx][row];               // (k=k0+tx, h=h0+row)
        __nv_bfloat16 lo = slo[tx][row];
        Wstk[base + k0 + tx]             = hi;         // seg0, coalesced along kv
        Wstk[base + Kdim + k0 + tx]      = lo;         // seg1
        Wstk[base + 2 * Kdim + k0 + tx]  = hi;         // seg2
    }
}

__global__ __launch_bounds__(256) void neg_a_kernel(const float* __restrict__ Alog,
                                                    float* __restrict__ negA)
{
    int h = blockIdx.x * blockDim.x + threadIdx.x;
    if (h < H_DIM) negA[h] = -expf(Alog[h]);
}

__global__ __launch_bounds__(256) void split_x_kernel(
    const float* __restrict__ x, __nv_bfloat16* __restrict__ xhi,
    __nv_bfloat16* __restrict__ xlo, size_t n)
{
    size_t idx = (size_t)blockIdx.x * blockDim.x + threadIdx.x;
    if (idx >= n) return;
    float v = x[idx];
    __nv_bfloat16 hi = __float2bfloat16(v);
    xhi[idx] = hi;
    xlo[idx] = __float2bfloat16(v - __bfloat162float(hi));
}

// ---------------- mma.sync fused projection GEMM ----------------------------
// C_full[t][n] = sum_kv A[t][kv] * Wstk[n][kv], A = [Xhi | Xhi | Xlo]
// CTA tile: 128 (t) x 256 (packed n) x 32 (k). 8 warps: 2 in m, 4 in n.
// Warp tile 64x64 = 4 m16-frags x 8 n8-frags (128 acc regs, 1 CTA/SM).
// 128 B of LDSM traffic per MMA -> smem crossbar roughly balanced vs HMMA.
// 4-stage cp.async pipeline; ONE __syncthreads per 32-k iteration.
// Smem rows padded to 80B: conflict-free ldmatrix.
#define ROWB 80
#define STG  (384 * ROWB)              // A(128 rows) + B(256 rows) = 30720 B
#define NSTAGE 4
#define PROJ_SMEM (NSTAGE * STG)       // 122880 B
__global__ __launch_bounds__(256, 1) void proj_mma_kernel(
    const __nv_bfloat16* __restrict__ Xhi,
    const __nv_bfloat16* __restrict__ Xlo,
    const __nv_bfloat16* __restrict__ Wstk,
    const float* __restrict__ negA,
    int Kdim,
    float* __restrict__ outA, float* __restrict__ outBx, float* __restrict__ outC)
{
    extern __shared__ __align__(16) char sm[];
    const uint32_t sbase = smem_u32(sm);
    const int tid  = threadIdx.x;
    const int wid  = tid >> 5;
    const int lane = tid & 31;
    const int wm = wid & 1;           // m-warp: rows wm*64
    const int wn = wid >> 1;          // n-warp: cols wn*64
    const int n0 = blockIdx.x * 256;  // packed-col base
    const int m0 = blockIdx.y * 128;  // t base
    const int Kv = 3 * Kdim;
    const int NCH = Kv / 32;

    // global->smem copy: 1536 16B-chunks per stage, 6 per thread
    // chunk c: row c>>2 (0..383), sub c&3. rows 0..127 = A, 128..383 = B.
    float acc[4][8][4];
    #pragma unroll
    for (int mf = 0; mf < 4; mf++)
        #pragma unroll
        for (int nf = 0; nf < 8; nf++)
            #pragma unroll
            for (int q = 0; q < 4; q++) acc[mf][nf][q] = 0.f;

    auto load_stage = [&](int kc, int st) {
        int kv = kc * 32;
        int seg = (kv >= 2 * Kdim) ? 2 : ((kv >= Kdim) ? 1 : 0);
        int ks = kv - seg * Kdim;
        const __nv_bfloat16* Asrc = (seg < 2) ? Xhi : Xlo;
        const uint32_t sst = sbase + st * STG;
        #pragma unroll
        for (int i = 0; i < 6; i++) {
            int c = tid + 256 * i;
            int row = c >> 2, sub = c & 3;
            uint32_t sa = sst + (uint32_t)row * ROWB + (uint32_t)sub * 16;
            if (row < 128) {
                cp16(sa, Asrc + (size_t)(m0 + row) * Kdim + ks + sub * 8);
            } else {
                cp16(sa, Wstk + (size_t)(n0 + row - 128) * Kv + kv + sub * 8);
            }
        }
    };

    // ldmatrix per-lane addressing
    const int r16 = lane & 15;
    const int cb16 = (lane >> 4) * 16;   // 0 or 16 bytes (k 0-7 / 8-15)
    const uint32_t a_lm0 = (uint32_t)(wm * 64 + r16) * ROWB + cb16;
    const uint32_t b_lm0 = (uint32_t)(128 + wn * 64 + r16) * ROWB + cb16;

    // prologue: fill 3 of the 4 stages
    load_stage(0, 0); cp_commit();
    load_stage(1, 1); cp_commit();
    load_stage(2, 2); cp_commit();

    int st = 0;
    for (int kc = 0; kc < NCH; kc++) {
        cp_wait2();            // group kc complete (<=2 pending: kc+1, kc+2)
        __syncthreads();       // data visible; stage consumed last iter is free

        // prefetch kc+3 into (kc+3)%4 — the stage freed by the barrier
        if (kc + 3 < NCH) {
            int pst = st + 3; if (pst >= NSTAGE) pst -= NSTAGE;
            load_stage(kc + 3, pst);
        }
        cp_commit();

        const uint32_t sA = sbase + st * STG;
        #pragma unroll
        for (int kstep = 0; kstep < 2; kstep++) {
            const uint32_t kb = kstep * 32;
            uint32_t afr[4][4], bfr[8][2];
            #pragma unroll
            for (int mf = 0; mf < 4; mf++)
                ldm_x4(sA + a_lm0 + (uint32_t)mf * 16 * ROWB + kb,
                       afr[mf][0], afr[mf][1], afr[mf][2], afr[mf][3]);
            #pragma unroll
            for (int np = 0; np < 4; np++) {
                uint32_t r0, r1, r2, r3;
                ldm_x4(sA + b_lm0 + (uint32_t)np * 16 * ROWB + kb, r0, r1, r2, r3);
                bfr[2 * np][0] = r0; bfr[2 * np + 1][0] = r1;
                bfr[2 * np][1] = r2; bfr[2 * np + 1][1] = r3;
            }
            #pragma unroll
            for (int mf = 0; mf < 4; mf++)
                #pragma unroll
                for (int nf = 0; nf < 8; nf++)
                    mma_bf16(acc[mf][nf], afr[mf], bfr[nf]);
        }

        if (++st == NSTAGE) st = 0;
    }

    // Epilogue — fragment-native packed-column handling.
    // D frag (m16n8 f32): c0:(g, 2q) c1:(g, 2q+1) c2:(g+8, 2q) c3:(g+8, 2q+1),
    // g = lane>>2, q = lane&3. Packed n = 4h+p: even q -> (xs, B); odd q -> (C, d).
    const int g = lane >> 2, q = lane & 3;
    #pragma unroll
    for (int mf = 0; mf < 4; mf++) {
        const int t0 = m0 + wm * 64 + mf * 16 + g;
        #pragma unroll
        for (int nf = 0; nf < 8; nf++) {
            const int nb = n0 + wn * 64 + nf * 8;
            const int h = (nb >> 2) + (q >> 1);
            const float* a4 = acc[mf][nf];
            if ((q & 1) == 0) {
                outBx[(size_t)t0 * H_DIM + h]       = a4[0] * a4[1];
                outBx[(size_t)(t0 + 8) * H_DIM + h] = a4[2] * a4[3];
            } else {
                const float na = __ldg(&negA[h]);
                outC[(size_t)t0 * H_DIM + h]       = a4[0];
                outC[(size_t)(t0 + 8) * H_DIM + h] = a4[2];
                float d0 = 1.f / (1.f + expf(-a4[1]));
                float d1 = 1.f / (1.f + expf(-a4[3]));
                outA[(size_t)t0 * H_DIM + h]       = expf(na * d0);
                outA[(size_t)(t0 + 8) * H_DIM + h] = expf(na * d1);
            }
        }
    }
}

// ---------------- scan kernels ----------------------------------------------
__global__ __launch_bounds__(256) void scan1_kernel(
    const float* __restrict__ A, const float* __restrict__ Bx,
    float* __restrict__ chA, float* __restrict__ chH)
{
    int idx = blockIdx.x * blockDim.x + threadIdx.x;
    int ch = idx & (H_DIM - 1);
    int chunk = idx / H_DIM;
    const float* pA = A  + (size_t)chunk * CH_L * H_DIM + ch;
    const float* pB = Bx + (size_t)chunk * CH_L * H_DIM + ch;
    float ap = 1.f, h = 0.f;
    #pragma unroll 8
    for (int i = 0; i < CH_L; i++) {
        float a = pA[(size_t)i * H_DIM];
        float b = pB[(size_t)i * H_DIM];
        h = fmaf(a, h, b);
        ap *= a;
    }
    chA[idx] = ap;
    chH[idx] = h;
}

// Per-channel Kogge-Stone scan over chunk summaries (affine composition).
__global__ __launch_bounds__(NCHUNK) void scan2_kernel(
    const float* __restrict__ chA, const float* __restrict__ chH,
    float* __restrict__ carry)
{
    __shared__ float sA[NCHUNK], sH[NCHUNK];
    const int ch = blockIdx.x;
    const int j = threadIdx.x;
    float a = chA[j * H_DIM + ch];
    float h = chH[j * H_DIM + ch];
    sA[j] = a; sH[j] = h;
    __syncthreads();
    #pragma unroll
    for (int off = 1; off < NCHUNK; off <<= 1) {
        float pa = 0.f, ph = 0.f;
        if (j >= off) { pa = sA[j - off]; ph = sH[j - off]; }
        __syncthreads();
        if (j >= off) { h = fmaf(a, ph, h); a *= pa; }
        sA[j] = a; sH[j] = h;
        __syncthreads();
    }
    carry[j * H_DIM + ch] = (j == 0) ? 0.f : sH[j - 1];
}

__global__ __launch_bounds__(256) void scan3_kernel(
    const float* __restrict__ A, const float* __restrict__ Bx,
    const float* __restrict__ C, const float* __restrict__ carry,
    float* __restrict__ y, __nv_bfloat16* __restrict__ yhi,
    __nv_bfloat16* __restrict__ ylo, int mode)
{
    int idx = blockIdx.x * blockDim.x + threadIdx.x;
    int ch = idx & (H_DIM - 1);
    int chunk = idx / H_DIM;
    size_t base = (size_t)chunk * CH_L * H_DIM + ch;
    float h = carry[idx];
    #pragma unroll 8
    for (int i = 0; i < CH_L; i++) {
        size_t off = base + (size_t)i * H_DIM;
        float a = A[off];
        h = fmaf(a, h, Bx[off]);
        float v = C[off] * h;
        if (mode == 0) {
            __nv_bfloat16 hi = __float2bfloat16(v);
            yhi[off] = hi;
            ylo[off] = __float2bfloat16(v - __bfloat162float(hi));
        } else {
            y[off] = v;
        }
    }
}

// ---------------- output head -----------------------------------------------
__global__ __launch_bounds__(256) void final_kernel(
    const float* __restrict__ y1, const float* __restrict__ x,
    const float* __restrict__ Wout, const float* __restrict__ bout,
    const float* __restrict__ Wskip, float* __restrict__ out)
{
    int gwarp = (blockIdx.x * blockDim.x + threadIdx.x) >> 5;
    int lane = threadIdx.x & 31;
    if (gwarp >= T_DIM) return;

    float a0 = 0.f, a1 = 0.f, a2 = 0.f, a3 = 0.f;
    const float* yr = y1 + (size_t)gwarp * H_DIM;
    const float4* Wo4 = (const float4*)Wout;
    #pragma unroll 4
    for (int h = lane; h < H_DIM; h += 32) {
        float v = yr[h];
        float4 w = Wo4[h];
        a0 = fmaf(v, w.x, a0); a1 = fmaf(v, w.y, a1);
        a2 = fmaf(v, w.z, a2); a3 = fmaf(v, w.w, a3);
    }
    const float* xr = x + (size_t)gwarp * OBS_DIM;
    const float4* Ws4 = (const float4*)Wskip;
    #pragma unroll 4
    for (int k = lane; k < OBS_DIM; k += 32) {
        float v = xr[k];
        float4 w = Ws4[k];
        a0 = fmaf(v, w.x, a0); a1 = fmaf(v, w.y, a1);
        a2 = fmaf(v, w.z, a2); a3 = fmaf(v, w.w, a3);
    }
    #pragma unroll
    for (int off = 16; off > 0; off >>= 1) {
        a0 += __shfl_xor_sync(0xFFFFFFFFu, a0, off);
        a1 += __shfl_xor_sync(0xFFFFFFFFu, a1, off);
        a2 += __shfl_xor_sync(0xFFFFFFFFu, a2, off);
        a3 += __shfl_xor_sync(0xFFFFFFFFu, a3, off);
    }
    if (lane == 0) {
        float* o = out + (size_t)gwarp * NOBJ_DIM;
        o[0] = a0 + bout[0];
        o[1] = a1 + bout[1];
        o[2] = a2 + bout[2];
        o[3] = a3 + bout[3];
    }
}

// ---------------- launch ----------------------------------------------------
extern "C" void kernel_launch(void* const* d_in, const int* in_sizes, int n_in,
                              void* d_out, int out_size)
{
    const float* x      = (const float*)d_in[0];
    const float* Win0   = (const float*)d_in[1];
    const float* WB0    = (const float*)d_in[2];
    const float* WC0    = (const float*)d_in[3];
    const float* Wd0    = (const float*)d_in[4];
    const float* Alog0  = (const float*)d_in[5];
    const float* Win1   = (const float*)d_in[6];
    const float* WB1    = (const float*)d_in[7];
    const float* WC1    = (const float*)d_in[8];
    const float* Wd1    = (const float*)d_in[9];
    const float* Alog1  = (const float*)d_in[10];
    const float* Wout   = (const float*)d_in[11];
    const float* bout   = (const float*)d_in[12];
    const float* Wskip  = (const float*)d_in[13];
    float* out = (float*)d_out;

    float *pA, *pBx, *pC, *pY, *pchA, *pchH, *pcar, *pnegA;
    __nv_bfloat16 *pXhi, *pXlo, *pWstk;
    cudaGetSymbolAddress((void**)&pA,    g_ABar);
    cudaGetSymbolAddress((void**)&pBx,   g_Bx);
    cudaGetSymbolAddress((void**)&pC,    g_C);
    cudaGetSymbolAddress((void**)&pY,    g_y);
    cudaGetSymbolAddress((void**)&pchA,  g_chA);
    cudaGetSymbolAddress((void**)&pchH,  g_chH);
    cudaGetSymbolAddress((void**)&pcar,  g_carry);
    cudaGetSymbolAddress((void**)&pnegA, g_negA);
    cudaGetSymbolAddress((void**)&pXhi,  g_Xhi);
    cudaGetSymbolAddress((void**)&pXlo,  g_Xlo);
    cudaGetSymbolAddress((void**)&pWstk, g_Wstk);

    cudaFuncSetAttribute(proj_mma_kernel,
                         cudaFuncAttributeMaxDynamicSharedMemorySize, PROJ_SMEM);

    dim3 pgrid(8, T_DIM / 128);           // n-tiles fastest -> A-slab L2 reuse
    int scan_blocks = (NCHUNK * H_DIM) / 256;
    dim3 packb(32, 8);

    // ---- layer 0 (Kdim = 256, Kv = 768)
    pack_w_kernel<<<dim3(OBS_DIM / 32, H_DIM / 32, 4), packb>>>(Win0, WB0, WC0, Wd0, OBS_DIM, pWstk);
    neg_a_kernel<<<2, 256>>>(Alog0, pnegA);
    split_x_kernel<<<(T_DIM * OBS_DIM) / 256, 256>>>(x, pXhi, pXlo, (size_t)T_DIM * OBS_DIM);
    proj_mma_kernel<<<pgrid, 256, PROJ_SMEM>>>(pXhi, pXlo, pWstk, pnegA, OBS_DIM, pA, pBx, pC);
    scan1_kernel<<<scan_blocks, 256>>>(pA, pBx, pchA, pchH);
    scan2_kernel<<<H_DIM, NCHUNK>>>(pchA, pchH, pcar);
    scan3_kernel<<<scan_blocks, 256>>>(pA, pBx, pC, pcar, nullptr, pXhi, pXlo, 0);

    // ---- layer 1 (Kdim = 512, Kv = 1536)
    pack_w_kernel<<<dim3(H_DIM / 32, H_DIM / 32, 4), packb>>>(Win1, WB1, WC1, Wd1, H_DIM, pWstk);
    neg_a_kernel<<<2, 256>>>(Alog1, pnegA);
    proj_mma_kernel<<<pgrid, 256, PROJ_SMEM>>>(pXhi, pXlo, pWstk, pnegA, H_DIM, pA, pBx, pC);
    scan1_kernel<<<scan_blocks, 256>>>(pA, pBx, pchA, pchH);
    scan2_kernel<<<H_DIM, NCHUNK>>>(pchA, pchH, pcar);
    scan3_kernel<<<scan_blocks, 256>>>(pA, pBx, pC, pcar, pY, nullptr, nullptr, 1);

    // ---- output head
    final_kernel<<<T_DIM / 8, 256>>>(pY, x, Wout, bout, Wskip, out);
}

// round 16
// speedup vs baseline: 1.0662x; 1.0662x over previous
#include <cuda_runtime.h>
#include <cuda_bf16.h>
#include <math.h>
#include <stdint.h>

#define T_DIM 32768
#define OBS_DIM 256
#define H_DIM 512
#define NOBJ_DIM 4
#define CH_L 64
#define NCHUNK (T_DIM / CH_L)   // 512

// ---------------- device-global scratch (no runtime allocation) -------------
__device__ float g_ABar[(size_t)T_DIM * H_DIM];
__device__ float g_Bx  [(size_t)T_DIM * H_DIM];
__device__ float g_C   [(size_t)T_DIM * H_DIM];
__device__ float g_y   [(size_t)T_DIM * H_DIM];
__device__ __nv_bfloat16 g_Xhi[(size_t)T_DIM * H_DIM];
__device__ __nv_bfloat16 g_Xlo[(size_t)T_DIM * H_DIM];
__device__ __nv_bfloat16 g_Wstk[(size_t)2048 * 1536];   // [n_packed][Kv]
__device__ float g_negA[H_DIM];
__device__ float g_chA [NCHUNK * H_DIM];
__device__ float g_chH [NCHUNK * H_DIM];
__device__ float g_carry[NCHUNK * H_DIM];

// ---------------- PTX helpers (plain sm_103 features only) ------------------
__device__ __forceinline__ uint32_t smem_u32(const void* p) {
    uint32_t a;
    asm("{ .reg .u64 t; cvta.to.shared.u64 t, %1; cvt.u32.u64 %0, t; }" : "=r"(a) : "l"(p));
    return a;
}
__device__ __forceinline__ void cp16(uint32_t saddr, const void* gaddr) {
    asm volatile("cp.async.cg.shared.global [%0], [%1], 16;" :: "r"(saddr), "l"(gaddr) : "memory");
}
__device__ __forceinline__ void cp_commit() {
    asm volatile("cp.async.commit_group;" ::: "memory");
}
__device__ __forceinline__ void cp_wait2() {
    asm volatile("cp.async.wait_group 2;" ::: "memory");
}
__device__ __forceinline__ void ldm_x4(uint32_t addr, uint32_t& r0, uint32_t& r1,
                                       uint32_t& r2, uint32_t& r3) {
    asm volatile("ldmatrix.sync.aligned.m8n8.x4.shared.b16 {%0,%1,%2,%3}, [%4];"
                 : "=r"(r0), "=r"(r1), "=r"(r2), "=r"(r3) : "r"(addr));
}
__device__ __forceinline__ void mma_bf16(float* d, const uint32_t* a, const uint32_t* b) {
    asm volatile(
        "mma.sync.aligned.m16n8k16.row.col.f32.bf16.bf16.f32 "
        "{%0,%1,%2,%3}, {%4,%5,%6,%7}, {%8,%9}, {%0,%1,%2,%3};"
        : "+f"(d[0]), "+f"(d[1]), "+f"(d[2]), "+f"(d[3])
        : "r"(a[0]), "r"(a[1]), "r"(a[2]), "r"(a[3]), "r"(b[0]), "r"(b[1]));
}

// ---------------- preprocessing kernels -------------------------------------
// Pack 4 weight mats [K,H] fp32 -> Wstk[n][Kv] bf16, n = 4*h+p, Kv = 3K:
// seg0: hi(W), seg1: lo(W), seg2: hi(W)   (pairs with A = [Xhi | Xhi | Xlo])
__global__ __launch_bounds__(256) void pack_w_kernel(
    const float* __restrict__ Win, const float* __restrict__ WB,
    const float* __restrict__ WC,  const float* __restrict__ Wd,
    int Kdim, __nv_bfloat16* __restrict__ Wstk)
{
    __shared__ __nv_bfloat16 shi[32][33];
    __shared__ __nv_bfloat16 slo[32][33];
    const int p  = blockIdx.z;
    const int k0 = blockIdx.x * 32;
    const int h0 = blockIdx.y * 32;
    const int tx = threadIdx.x, ty = threadIdx.y;
    const int Kv = 3 * Kdim;
    const float* Wp = (p == 0) ? Win : (p == 1) ? WB : (p == 2) ? WC : Wd;

    #pragma unroll
    for (int i = 0; i < 4; i++) {
        int k = k0 + ty + 8 * i;
        float w = Wp[(size_t)k * H_DIM + h0 + tx];    // coalesced along h
        __nv_bfloat16 hi = __float2bfloat16(w);
        shi[ty + 8 * i][tx] = hi;
        slo[ty + 8 * i][tx] = __float2bfloat16(w - __bfloat162float(hi));
    }
    __syncthreads();

    #pragma unroll
    for (int i = 0; i < 4; i++) {
        int row = ty + 8 * i;                          // h offset in tile
        size_t base = (size_t)(4 * (h0 + row) + p) * Kv;
        __nv_bfloat16 hi = shi[tx][row];               // (k=k0+tx, h=h0+row)
        __nv_bfloat16 lo = slo[tx][row];
        Wstk[base + k0 + tx]             = hi;         // seg0, coalesced along kv
        Wstk[base + Kdim + k0 + tx]      = lo;         // seg1
        Wstk[base + 2 * Kdim + k0 + tx]  = hi;         // seg2
    }
}

__global__ __launch_bounds__(256) void neg_a_kernel(const float* __restrict__ Alog,
                                                    float* __restrict__ negA)
{
    int h = blockIdx.x * blockDim.x + threadIdx.x;
    if (h < H_DIM) negA[h] = -expf(Alog[h]);
}

__global__ __launch_bounds__(256) void split_x_kernel(
    const float* __restrict__ x, __nv_bfloat16* __restrict__ xhi,
    __nv_bfloat16* __restrict__ xlo, size_t n)
{
    size_t idx = (size_t)blockIdx.x * blockDim.x + threadIdx.x;
    if (idx >= n) return;
    float v = x[idx];
    __nv_bfloat16 hi = __float2bfloat16(v);
    xhi[idx] = hi;
    xlo[idx] = __float2bfloat16(v - __bfloat162float(hi));
}

// ---------------- mma.sync fused projection GEMM ----------------------------
// C_full[t][n] = sum_kv A[t][kv] * Wstk[n][kv], A = [Xhi | Xhi | Xlo]
// CTA tile: 128 (t) x 64 (packed n) x 32 (k). 8 warps: 4 in m, 2 in n.
// Warp tile 32x32. 4-stage cp.async pipeline; one __syncthreads per 32 k.
// Epilogue ALSO computes per-(chunk, h) scan summaries inline (replaces scan1):
// the pipeline smem is reused as a [128][17] staging tile after the mainloop.
#define ROWB 80
#define STG  (192 * ROWB)              // A(128 rows) + B(64 rows) = 15360 B
#define NSTAGE 4
#define PROJ_SMEM (NSTAGE * STG)       // 61440 B
__global__ __launch_bounds__(256, 3) void proj_mma_kernel(
    const __nv_bfloat16* __restrict__ Xhi,
    const __nv_bfloat16* __restrict__ Xlo,
    const __nv_bfloat16* __restrict__ Wstk,
    const float* __restrict__ negA,
    int Kdim,
    float* __restrict__ outA, float* __restrict__ outBx, float* __restrict__ outC,
    float* __restrict__ chA, float* __restrict__ chH)
{
    extern __shared__ __align__(16) char sm[];
    const uint32_t sbase = smem_u32(sm);
    const int tid  = threadIdx.x;
    const int wid  = tid >> 5;
    const int lane = tid & 31;
    const int wm = wid & 3;           // m-warp: rows wm*32
    const int wn = wid >> 2;          // n-warp: cols wn*32
    const int n0 = blockIdx.x * 64;   // packed-col base
    const int m0 = blockIdx.y * 128;  // t base
    const int Kv = 3 * Kdim;
    const int NCH = Kv / 32;

    const int ar0 = tid >> 2;             // copy row index base
    const int asb = tid & 3;

    float acc[2][4][4];
    #pragma unroll
    for (int mf = 0; mf < 2; mf++)
        #pragma unroll
        for (int nf = 0; nf < 4; nf++)
            #pragma unroll
            for (int q = 0; q < 4; q++) acc[mf][nf][q] = 0.f;

    auto load_stage = [&](int kc, int st) {
        int kv = kc * 32;
        int seg = (kv >= 2 * Kdim) ? 2 : ((kv >= Kdim) ? 1 : 0);
        int ks = kv - seg * Kdim;
        const __nv_bfloat16* Asrc = (seg < 2) ? Xhi : Xlo;
        const uint32_t sst = sbase + st * STG;
        // A: rows 0..127
        cp16(sst + (uint32_t)ar0 * ROWB + asb * 16,
             Asrc + (size_t)(m0 + ar0) * Kdim + ks + asb * 8);
        cp16(sst + (uint32_t)(ar0 + 64) * ROWB + asb * 16,
             Asrc + (size_t)(m0 + ar0 + 64) * Kdim + ks + asb * 8);
        // B: rows 0..63
        cp16(sst + (uint32_t)(128 + ar0) * ROWB + asb * 16,
             Wstk + (size_t)(n0 + ar0) * Kv + kv + asb * 8);
    };

    const int r16 = lane & 15;
    const int cb16 = (lane >> 4) * 16;
    const uint32_t a_lm0 = (uint32_t)(wm * 32 + r16) * ROWB + cb16;
    const uint32_t b_lm0 = (uint32_t)(128 + wn * 32 + r16) * ROWB + cb16;

    load_stage(0, 0); cp_commit();
    load_stage(1, 1); cp_commit();
    load_stage(2, 2); cp_commit();

    int st = 0;
    for (int kc = 0; kc < NCH; kc++) {
        cp_wait2();
        __syncthreads();

        if (kc + 3 < NCH) {
            int pst = st + 3; if (pst >= NSTAGE) pst -= NSTAGE;
            load_stage(kc + 3, pst);
        }
        cp_commit();

        const uint32_t sA = sbase + st * STG;
        #pragma unroll
        for (int kstep = 0; kstep < 2; kstep++) {
            const uint32_t kb = kstep * 32;
            uint32_t afr[2][4], bfr[4][2];
            #pragma unroll
            for (int mf = 0; mf < 2; mf++)
                ldm_x4(sA + a_lm0 + (uint32_t)mf * 16 * ROWB + kb,
                       afr[mf][0], afr[mf][1], afr[mf][2], afr[mf][3]);
            #pragma unroll
            for (int np = 0; np < 2; np++) {
                uint32_t r0, r1, r2, r3;
                ldm_x4(sA + b_lm0 + (uint32_t)np * 16 * ROWB + kb, r0, r1, r2, r3);
                bfr[2 * np][0] = r0; bfr[2 * np + 1][0] = r1;
                bfr[2 * np][1] = r2; bfr[2 * np + 1][1] = r3;
            }
            #pragma unroll
            for (int mf = 0; mf < 2; mf++)
                #pragma unroll
                for (int nf = 0; nf < 4; nf++)
                    mma_bf16(acc[mf][nf], afr[mf], bfr[nf]);
        }

        if (++st == NSTAGE) st = 0;
    }

    // All cp.async groups that carried data are complete (tail groups were
    // empty); after this barrier the pipeline smem is reusable for staging.
    __syncthreads();
    float* sAb = (float*)sm;               // [128][17] A_bar staging
    float* sBb = sAb + 128 * 17;           // [128][17] Bx staging

    // Epilogue — fragment-native packed-column handling + smem staging.
    // g = lane>>2, q = lane&3. Packed n = 4h+p: even q -> (xs, B); odd q -> (C, d).
    const int g = lane >> 2, q = lane & 3;
    #pragma unroll
    for (int mf = 0; mf < 2; mf++) {
        const int tl = wm * 32 + mf * 16 + g;          // local t (0..127)
        const int t0 = m0 + tl;
        #pragma unroll
        for (int nf = 0; nf < 4; nf++) {
            const int hl = wn * 8 + nf * 2 + (q >> 1); // local h (0..15)
            const int h  = (n0 >> 2) + hl;
            const float* a4 = acc[mf][nf];
            if ((q & 1) == 0) {
                float b0 = a4[0] * a4[1];
                float b1 = a4[2] * a4[3];
                outBx[(size_t)t0 * H_DIM + h]       = b0;
                outBx[(size_t)(t0 + 8) * H_DIM + h] = b1;
                sBb[tl * 17 + hl]       = b0;
                sBb[(tl + 8) * 17 + hl] = b1;
            } else {
                const float na = __ldg(&negA[h]);
                outC[(size_t)t0 * H_DIM + h]       = a4[0];
                outC[(size_t)(t0 + 8) * H_DIM + h] = a4[2];
                float d0 = __fdividef(1.f, 1.f + __expf(-a4[1]));
                float d1 = __fdividef(1.f, 1.f + __expf(-a4[3]));
                float A0 = __expf(na * d0);
                float A1 = __expf(na * d1);
                outA[(size_t)t0 * H_DIM + h]       = A0;
                outA[(size_t)(t0 + 8) * H_DIM + h] = A1;
                sAb[tl * 17 + hl]       = A0;
                sAb[(tl + 8) * 17 + hl] = A1;
            }
        }
    }
    __syncthreads();

    // One warp: per-(chunk, h) serial summary over 64 steps (replaces scan1).
    if (tid < 32) {
        const int chunk = tid >> 4;        // 0 or 1
        const int hl = tid & 15;
        float ap = 1.f, hh = 0.f;
        #pragma unroll 8
        for (int i = 0; i < CH_L; i++) {
            int tl = chunk * 64 + i;
            float a = sAb[tl * 17 + hl];
            hh = fmaf(a, hh, sBb[tl * 17 + hl]);
            ap *= a;
        }
        int gchunk = (m0 >> 6) + chunk;
        int hg = (n0 >> 2) + hl;
        chA[gchunk * H_DIM + hg] = ap;
        chH[gchunk * H_DIM + hg] = hh;
    }
}

// ---------------- scan kernels ----------------------------------------------
// Per-channel Kogge-Stone scan over chunk summaries (affine composition).
__global__ __launch_bounds__(NCHUNK) void scan2_kernel(
    const float* __restrict__ chA, const float* __restrict__ chH,
    float* __restrict__ carry)
{
    __shared__ float sA[NCHUNK], sH[NCHUNK];
    const int ch = blockIdx.x;
    const int j = threadIdx.x;
    float a = chA[j * H_DIM + ch];
    float h = chH[j * H_DIM + ch];
    sA[j] = a; sH[j] = h;
    __syncthreads();
    #pragma unroll
    for (int off = 1; off < NCHUNK; off <<= 1) {
        float pa = 0.f, ph = 0.f;
        if (j >= off) { pa = sA[j - off]; ph = sH[j - off]; }
        __syncthreads();
        if (j >= off) { h = fmaf(a, ph, h); a *= pa; }
        sA[j] = a; sH[j] = h;
        __syncthreads();
    }
    carry[j * H_DIM + ch] = (j == 0) ? 0.f : sH[j - 1];
}

__global__ __launch_bounds__(256) void scan3_kernel(
    const float* __restrict__ A, const float* __restrict__ Bx,
    const float* __restrict__ C, const float* __restrict__ carry,
    float* __restrict__ y, __nv_bfloat16* __restrict__ yhi,
    __nv_bfloat16* __restrict__ ylo, int mode)
{
    int idx = blockIdx.x * blockDim.x + threadIdx.x;
    int ch = idx & (H_DIM - 1);
    int chunk = idx / H_DIM;
    size_t base = (size_t)chunk * CH_L * H_DIM + ch;
    float h = carry[idx];
    #pragma unroll 8
    for (int i = 0; i < CH_L; i++) {
        size_t off = base + (size_t)i * H_DIM;
        float a = A[off];
        h = fmaf(a, h, Bx[off]);
        float v = C[off] * h;
        if (mode == 0) {
            __nv_bfloat16 hi = __float2bfloat16(v);
            yhi[off] = hi;
            ylo[off] = __float2bfloat16(v - __bfloat162float(hi));
        } else {
            y[off] = v;
        }
    }
}

// ---------------- output head -----------------------------------------------
__global__ __launch_bounds__(256) void final_kernel(
    const float* __restrict__ y1, const float* __restrict__ x,
    const float* __restrict__ Wout, const float* __restrict__ bout,
    const float* __restrict__ Wskip, float* __restrict__ out)
{
    int gwarp = (blockIdx.x * blockDim.x + threadIdx.x) >> 5;
    int lane = threadIdx.x & 31;
    if (gwarp >= T_DIM) return;

    float a0 = 0.f, a1 = 0.f, a2 = 0.f, a3 = 0.f;
    const float* yr = y1 + (size_t)gwarp * H_DIM;
    const float4* Wo4 = (const float4*)Wout;
    #pragma unroll 4
    for (int h = lane; h < H_DIM; h += 32) {
        float v = yr[h];
        float4 w = Wo4[h];
        a0 = fmaf(v, w.x, a0); a1 = fmaf(v, w.y, a1);
        a2 = fmaf(v, w.z, a2); a3 = fmaf(v, w.w, a3);
    }
    const float* xr = x + (size_t)gwarp * OBS_DIM;
    const float4* Ws4 = (const float4*)Wskip;
    #pragma unroll 4
    for (int k = lane; k < OBS_DIM; k += 32) {
        float v = xr[k];
        float4 w = Ws4[k];
        a0 = fmaf(v, w.x, a0); a1 = fmaf(v, w.y, a1);
        a2 = fmaf(v, w.z, a2); a3 = fmaf(v, w.w, a3);
    }
    #pragma unroll
    for (int off = 16; off > 0; off >>= 1) {
        a0 += __shfl_xor_sync(0xFFFFFFFFu, a0, off);
        a1 += __shfl_xor_sync(0xFFFFFFFFu, a1, off);
        a2 += __shfl_xor_sync(0xFFFFFFFFu, a2, off);
        a3 += __shfl_xor_sync(0xFFFFFFFFu, a3, off);
    }
    if (lane == 0) {
        float* o = out + (size_t)gwarp * NOBJ_DIM;
        o[0] = a0 + bout[0];
        o[1] = a1 + bout[1];
        o[2] = a2 + bout[2];
        o[3] = a3 + bout[3];
    }
}

// ---------------- launch ----------------------------------------------------
extern "C" void kernel_launch(void* const* d_in, const int* in_sizes, int n_in,
                              void* d_out, int out_size)
{
    const float* x      = (const float*)d_in[0];
    const float* Win0   = (const float*)d_in[1];
    const float* WB0    = (const float*)d_in[2];
    const float* WC0    = (const float*)d_in[3];
    const float* Wd0    = (const float*)d_in[4];
    const float* Alog0  = (const float*)d_in[5];
    const float* Win1   = (const float*)d_in[6];
    const float* WB1    = (const float*)d_in[7];
    const float* WC1    = (const float*)d_in[8];
    const float* Wd1    = (const float*)d_in[9];
    const float* Alog1  = (const float*)d_in[10];
    const float* Wout   = (const float*)d_in[11];
    const float* bout   = (const float*)d_in[12];
    const float* Wskip  = (const float*)d_in[13];
    float* out = (float*)d_out;

    float *pA, *pBx, *pC, *pY, *pchA, *pchH, *pcar, *pnegA;
    __nv_bfloat16 *pXhi, *pXlo, *pWstk;
    cudaGetSymbolAddress((void**)&pA,    g_ABar);
    cudaGetSymbolAddress((void**)&pBx,   g_Bx);
    cudaGetSymbolAddress((void**)&pC,    g_C);
    cudaGetSymbolAddress((void**)&pY,    g_y);
    cudaGetSymbolAddress((void**)&pchA,  g_chA);
    cudaGetSymbolAddress((void**)&pchH,  g_chH);
    cudaGetSymbolAddress((void**)&pcar,  g_carry);
    cudaGetSymbolAddress((void**)&pnegA, g_negA);
    cudaGetSymbolAddress((void**)&pXhi,  g_Xhi);
    cudaGetSymbolAddress((void**)&pXlo,  g_Xlo);
    cudaGetSymbolAddress((void**)&pWstk, g_Wstk);

    cudaFuncSetAttribute(proj_mma_kernel,
                         cudaFuncAttributeMaxDynamicSharedMemorySize, PROJ_SMEM);

    dim3 pgrid(32, T_DIM / 128);          // n-tiles fastest -> A-slab L2 reuse
    int scan_blocks = (NCHUNK * H_DIM) / 256;
    dim3 packb(32, 8);

    // ---- layer 0 (Kdim = 256, Kv = 768)
    pack_w_kernel<<<dim3(OBS_DIM / 32, H_DIM / 32, 4), packb>>>(Win0, WB0, WC0, Wd0, OBS_DIM, pWstk);
    neg_a_kernel<<<2, 256>>>(Alog0, pnegA);
    split_x_kernel<<<(T_DIM * OBS_DIM) / 256, 256>>>(x, pXhi, pXlo, (size_t)T_DIM * OBS_DIM);
    proj_mma_kernel<<<pgrid, 256, PROJ_SMEM>>>(pXhi, pXlo, pWstk, pnegA, OBS_DIM,
                                               pA, pBx, pC, pchA, pchH);
    scan2_kernel<<<H_DIM, NCHUNK>>>(pchA, pchH, pcar);
    scan3_kernel<<<scan_blocks, 256>>>(pA, pBx, pC, pcar, nullptr, pXhi, pXlo, 0);

    // ---- layer 1 (Kdim = 512, Kv = 1536)
    pack_w_kernel<<<dim3(H_DIM / 32, H_DIM / 32, 4), packb>>>(Win1, WB1, WC1, Wd1, H_DIM, pWstk);
    neg_a_kernel<<<2, 256>>>(Alog1, pnegA);
    proj_mma_kernel<<<pgrid, 256, PROJ_SMEM>>>(pXhi, pXlo, pWstk, pnegA, H_DIM,
                                               pA, pBx, pC, pchA, pchH);
    scan2_kernel<<<H_DIM, NCHUNK>>>(pchA, pchH, pcar);
    scan3_kernel<<<scan_blocks, 256>>>(pA, pBx, pC, pcar, pY, nullptr, nullptr, 1);

    // ---- output head
    final_kernel<<<T_DIM / 8, 256>>>(pY, x, Wout, bout, Wskip, out);
}